// round 8
// baseline (speedup 1.0000x reference)
#include <cuda_runtime.h>
#include <cuda_fp16.h>
#include <cstdint>
#include <math.h>

// ---------------- scratch (static device globals; no allocation) ----------------
#define T_MAX 32768
#define NVAL 122              // 61 landmarks x 2 coords
#define ROWPAD 128            // halves per row (256 B)
#define NSEG 512
#define NF 4                  // frames per warp in kA
#define NWARP_A 8             // warps per kA block (256 threads)
#define NBLK_A 1024           // max kA blocks (T_MAX / (NWARP_A*NF))

__device__ __half    g_raw[(size_t)T_MAX * ROWPAD];   // fp16 staging (8 MB)
__device__ unsigned  g_keepbits[NBLK_A];              // one word per kA block (32 frames)
__device__ int       g_kept[T_MAX];
__device__ float     g_psum[80 * NBLK_A];             // [slot][block]
__device__ float     g_pcnt[80 * NBLK_A];
__device__ float     g_lipmean[80];
__device__ int       g_S;
__device__ float     g_sampled[NSEG * NVAL];
__device__ float     g_rowsum[NSEG];

// ---------------- kernel A: gather + hand transform + keep bits + lips partials ----------------
// 256 threads/block (reg cap 255 -> real load front-batching), lanes rebalanced:
//   lanes 0-20 : hand lh/rh loads (4/frame)
//   all lanes  : lips slot `lane` (2/frame)
//   lanes 24-31: lips slot 32+(lane-24) (2/frame)   [idle lanes take extra work]
__global__ __launch_bounds__(256) void kA(const float* __restrict__ frames,
                                          const int* __restrict__ lips_idx,
                                          int T) {
    __shared__ int      s_idx[40];
    __shared__ float    s_red[NWARP_A * 80];
    __shared__ float    s_redc[NWARP_A * 80];
    __shared__ unsigned s_kp[NWARP_A * NF];

    int tid  = threadIdx.x;
    int warp = tid >> 5;
    int lane = tid & 31;

    if (tid < 40) s_idx[tid] = lips_idx[tid];
    __syncthreads();

    bool hl = (lane < 21);
    bool l2 = (lane >= 24);
    int i0 = s_idx[lane];
    int i1 = l2 ? s_idx[32 + (lane - 24)] : 0;

    int base = (blockIdx.x * NWARP_A + warp) * NF;

    float lx[NF], ly[NF], rx[NF], ry[NF];
    float x0[NF], y0[NF], x1[NF], y1[NF];

    // ---- phase 1: issue every load for all NF frames, no dependent compute ----
    #pragma unroll
    for (int j = 0; j < NF; j++) {
        int t = base + j;
        bool valid = (t < T);
        const float* f = frames + (size_t)(valid ? t : 0) * (543 * 3);
        lx[j] = ly[j] = rx[j] = ry[j] = 0.f;
        x0[j] = y0[j] = x1[j] = y1[j] = 0.f;
        if (valid && hl) {
            lx[j] = f[(468 + lane) * 3 + 0];
            ly[j] = f[(468 + lane) * 3 + 1];
            rx[j] = f[(522 + lane) * 3 + 0];
            ry[j] = f[(522 + lane) * 3 + 1];
        }
        if (valid) { x0[j] = f[i0 * 3 + 0]; y0[j] = f[i0 * 3 + 1]; }
        if (valid && l2) { x1[j] = f[i1 * 3 + 0]; y1[j] = f[i1 * 3 + 1]; }
    }

    // ---- phase 2: compute, reduce, store ----
    float ax0 = 0.f, ay0 = 0.f, ax1 = 0.f, ay1 = 0.f;
    float cx0 = 0.f, cy0 = 0.f, cx1 = 0.f, cy1 = 0.f;

    #pragma unroll
    for (int j = 0; j < NF; j++) {
        int t = base + j;
        bool valid = (t < T);

        float h0 = 0.f, h1 = 0.f;
        if (hl) {
            h0 = (isnan(lx[j]) ? 0.f : lx[j])         + (isnan(rx[j]) ? 0.f : (1.f - rx[j]));
            h1 = (isnan(ly[j]) ? 0.f : (1.f - ly[j])) + (isnan(ry[j]) ? 0.f : (1.f - ry[j]));
        }
        float s = h0 + h1;
        #pragma unroll
        for (int o = 16; o > 0; o >>= 1) s += __shfl_xor_sync(0xffffffffu, s, o);
        int kp = (s != 0.0f) ? 1 : 0;
        if (lane == 0) s_kp[warp * NF + j] = (unsigned)kp;

        if (valid) {
            __half* row = g_raw + (size_t)t * ROWPAD;
            if (hl)
                *reinterpret_cast<__half2*>(row + 2 * lane) = __floats2half2_rn(h0, h1);
            *reinterpret_cast<__half2*>(row + 42 + 2 * lane) = __floats2half2_rn(x0[j], y0[j]);
            if (l2)
                *reinterpret_cast<__half2*>(row + 106 + 2 * (lane - 24)) = __floats2half2_rn(x1[j], y1[j]);

            if (kp) {
                if (!isnan(x0[j])) { ax0 += x0[j]; cx0 += 1.f; }
                if (!isnan(y0[j])) { ay0 += y0[j]; cy0 += 1.f; }
                if (l2) {
                    if (!isnan(x1[j])) { ax1 += x1[j]; cx1 += 1.f; }
                    if (!isnan(y1[j])) { ay1 += y1[j]; cy1 += 1.f; }
                }
            }
        }
    }

    // --- per-warp partials -> shared ---
    s_red [warp * 80 + 2 * lane]     = ax0;
    s_red [warp * 80 + 2 * lane + 1] = ay0;
    s_redc[warp * 80 + 2 * lane]     = cx0;
    s_redc[warp * 80 + 2 * lane + 1] = cy0;
    if (l2) {
        int q = lane - 24;
        s_red [warp * 80 + 64 + 2 * q]     = ax1;
        s_red [warp * 80 + 64 + 2 * q + 1] = ay1;
        s_redc[warp * 80 + 64 + 2 * q]     = cx1;
        s_redc[warp * 80 + 64 + 2 * q + 1] = cy1;
    }
    __syncthreads();

    // keep bits: 32 frames/block -> exactly one ballot word
    if (tid < 32) {
        unsigned fl = s_kp[tid];
        unsigned bal = __ballot_sync(0xffffffffu, fl != 0u);
        if (tid == 0) g_keepbits[blockIdx.x] = bal;
    }

    // block reduce of lips partials -> global per-block slot (no atomics)
    if (tid < 80) {
        float sm = 0.f, cm = 0.f;
        #pragma unroll
        for (int w = 0; w < NWARP_A; w++) {
            sm += s_red [w * 80 + tid];
            cm += s_redc[w * 80 + tid];
        }
        g_psum[tid * NBLK_A + blockIdx.x] = sm;
        g_pcnt[tid * NBLK_A + blockIdx.x] = cm;
    }
}

// ---------------- kernel B: lip means + bitmask scan -> kept list + S ----------------
__global__ __launch_bounds__(1024) void kScan(int T, int nblk) {
    __shared__ int wtot[32];
    __shared__ int wexc[32];

    int tid = threadIdx.x, lane = tid & 31, w = tid >> 5;

    // part 1: reduce lips partials (warp per slot, coalesced)
    for (int s = w; s < 80; s += 32) {
        float sm = 0.f, cm = 0.f;
        for (int i = lane; i < nblk; i += 32) {
            sm += g_psum[s * NBLK_A + i];
            cm += g_pcnt[s * NBLK_A + i];
        }
        #pragma unroll
        for (int o = 16; o > 0; o >>= 1) {
            sm += __shfl_xor_sync(0xffffffffu, sm, o);
            cm += __shfl_xor_sync(0xffffffffu, cm, o);
        }
        if (lane == 0) g_lipmean[s] = (cm > 0.f) ? (sm / cm) : 0.f;
    }

    // part 2: one keep-word per thread
    int nwords = (T + 31) >> 5;
    unsigned word = (tid < nwords) ? g_keepbits[tid] : 0u;
    int c = __popc(word);

    int v = c;
    #pragma unroll
    for (int o = 1; o < 32; o <<= 1) {
        int n = __shfl_up_sync(0xffffffffu, v, o);
        if (lane >= o) v += n;
    }
    if (lane == 31) wtot[w] = v;
    __syncthreads();
    if (w == 0) {
        int x = wtot[lane];
        int inc = x;
        #pragma unroll
        for (int o = 1; o < 32; o <<= 1) {
            int n = __shfl_up_sync(0xffffffffu, inc, o);
            if (lane >= o) inc += n;
        }
        wexc[lane] = inc - x;
        if (lane == 31) g_S = inc;
    }
    __syncthreads();

    int off = (v - c) + wexc[w];
    int fb = tid << 5;
    while (word) {
        int b = __ffs(word) - 1;
        g_kept[off++] = fb + b;
        word &= (word - 1u);
    }
}

// ---------------- kernel C: segment means + row sums ----------------
__global__ __launch_bounds__(256) void kC() {
    __shared__ int   s_idx[96];
    __shared__ float s_part[128];
    __shared__ float s_val[128];

    int seg = blockIdx.x;
    int tid = threadIdx.x;
    int half = tid >> 7;
    int p = tid & 127;

    int S = g_S;
    long long D = (S > 0) ? (long long)(S - 1) : 0LL;
    int start = (int)(((long long)seg * D) >> 9);
    int end   = (int)(((long long)(seg + 1) * D) >> 9);
    int n = end - start;

    for (int r = tid; r < n; r += 256) s_idx[r] = g_kept[start + r];
    __syncthreads();

    float total = 0.0f;
    if (p < NVAL) {
        bool is_lip = (p >= 42);
        float m = is_lip ? g_lipmean[p - 42] : 0.0f;

        float s0 = 0.f, s1 = 0.f, s2 = 0.f, s3 = 0.f;
        int r = half;                      // half 0: even rows, half 1: odd rows
        for (; r + 6 < n; r += 8) {
            float v0 = __half2float(g_raw[(size_t)s_idx[r + 0] * ROWPAD + p]);
            float v1 = __half2float(g_raw[(size_t)s_idx[r + 2] * ROWPAD + p]);
            float v2 = __half2float(g_raw[(size_t)s_idx[r + 4] * ROWPAD + p]);
            float v3 = __half2float(g_raw[(size_t)s_idx[r + 6] * ROWPAD + p]);
            if (is_lip) {
                if (isnan(v0)) v0 = m;
                if (isnan(v1)) v1 = m;
                if (isnan(v2)) v2 = m;
                if (isnan(v3)) v3 = m;
            }
            s0 += v0; s1 += v1; s2 += v2; s3 += v3;
        }
        for (; r < n; r += 2) {
            float v = __half2float(g_raw[(size_t)s_idx[r] * ROWPAD + p]);
            if (is_lip && isnan(v)) v = m;
            s0 += v;
        }
        total = (s0 + s1) + (s2 + s3);
    }
    if (half == 1) s_part[p] = total;
    __syncthreads();

    float mean = 0.0f;
    if (half == 0) {
        if (p < NVAL) {
            mean = (n > 0) ? (total + s_part[p]) / (float)n : 0.0f;
            g_sampled[seg * NVAL + p] = mean;
        }
        s_val[p] = mean;   // 0 for p >= NVAL
    }
    __syncthreads();

    if (tid < 32) {
        float t = s_val[tid] + s_val[tid + 32] + s_val[tid + 64] + s_val[tid + 96];
        #pragma unroll
        for (int o = 16; o > 0; o >>= 1) t += __shfl_xor_sync(0xffffffffu, t, o);
        if (tid == 0) g_rowsum[seg] = t;
    }
}

// ---------------- kernel D: distributed compaction copy ----------------
__global__ __launch_bounds__(1024) void kD(float* __restrict__ out) {
    __shared__ int flg[NSEG];
    __shared__ int pos[NSEG];
    __shared__ int wtot[16];
    __shared__ int wexc[16];

    int tid = threadIdx.x, lane = tid & 31, w = tid >> 5;

    int f = 0, v = 0;
    if (tid < NSEG) {
        f = (g_rowsum[tid] != 0.0f) ? 1 : 0;
        v = f;
        #pragma unroll
        for (int o = 1; o < 32; o <<= 1) {
            int n = __shfl_up_sync(0xffffffffu, v, o);
            if (lane >= o) v += n;
        }
        if (lane == 31) wtot[w] = v;
    }
    __syncthreads();
    if (w == 0 && lane < 16) {
        int x = wtot[lane];
        int inc = x;
        #pragma unroll
        for (int o = 1; o < 16; o <<= 1) {
            int n = __shfl_up_sync(0x0000ffffu, inc, o);
            if (lane >= o) inc += n;
        }
        wexc[lane] = inc - x;
    }
    __syncthreads();

    if (tid < NSEG) {
        flg[tid] = f;
        pos[tid] = (v - f) + wexc[w];
    }
    __syncthreads();

    int e = blockIdx.x * 1024 + tid;
    if (e < NSEG * NVAL) {
        int row = e / NVAL;
        int col = e - row * NVAL;
        if (flg[row]) out[pos[row] * NVAL + col] = g_sampled[e];
    }
}

// ---------------- launch ----------------
extern "C" void kernel_launch(void* const* d_in, const int* in_sizes, int n_in,
                              void* d_out, int out_size) {
    const float* frames  = (const float*)d_in[0];
    const int*   lipsidx = (const int*)d_in[1];
    int T = in_sizes[0] / (543 * 3);
    if (T > T_MAX) T = T_MAX;

    int framesPerBlock = 32 * NF * NWARP_A / 32;   // NWARP_A * NF = 32
    int blocksA = (T + framesPerBlock - 1) / framesPerBlock;
    kA<<<blocksA, 256>>>(frames, lipsidx, T);
    kScan<<<1, 1024>>>(T, blocksA);
    kC<<<NSEG, 256>>>();
    int blocksD = (NSEG * NVAL + 1023) / 1024;
    kD<<<blocksD, 1024>>>((float*)d_out);
}